// round 1
// baseline (speedup 1.0000x reference)
#include <cuda_runtime.h>

#define NSEQ 512
#define L 64
#define NTOK (NSEQ*L)          // 32768
#define DM 128
#define DI 256
#define DS 16
#define DTR 8
#define XDBL_N (DTR + 2*DS)    // 40

// ---------------- scratch (no allocation allowed) ----------------
// offsets in floats
#define OFF_X     ((size_t)0)                         // NTOK*DM      = 4,194,304
#define OFF_XZ    (OFF_X    + (size_t)NTOK*DM)        // NTOK*2*DI    = 16,777,216
#define OFF_XC2   (OFF_XZ   + (size_t)NTOK*2*DI)      // NTOK*DI      = 8,388,608
#define OFF_XDBL  (OFF_XC2  + (size_t)NTOK*DI)        // NTOK*40      = 1,310,720
#define OFF_DT    (OFF_XDBL + (size_t)NTOK*XDBL_N)    // NTOK*DI
#define OFF_Y     (OFF_DT   + (size_t)NTOK*DI)        // NTOK*DI
#define OFF_O     (OFF_Y    + (size_t)NTOK*DI)        // NTOK*DM
#define OFF_STATS (OFF_O    + (size_t)NTOK*DM)        // 64
#define BUF_TOTAL (OFF_STATS + 64)

__device__ float g_buf[BUF_TOTAL];

// ---------------- generic fp32 GEMM: C[M,N] = A[M,K] @ W[N,K]^T ----------------
// BM=128, BN=64, BK=16, 256 threads, 8x4 per thread. M % 128 == 0, K % 16 == 0 assumed.
#define GBM 128
#define GBN 64
#define GBK 16

__global__ void __launch_bounds__(256) k_gemm(const float* __restrict__ A,
                                              const float* __restrict__ W,
                                              float* __restrict__ C,
                                              int M, int N, int K) {
    __shared__ float As[GBK][GBM + 4];
    __shared__ float Ws[GBK][GBN + 4];
    int bm = blockIdx.y * GBM;
    int bn = blockIdx.x * GBN;
    int tid = threadIdx.x;
    int tm = (tid >> 4) * 8;   // 0..120
    int tn = (tid & 15) * 4;   // 0..60

    float acc[8][4];
#pragma unroll
    for (int i = 0; i < 8; i++)
#pragma unroll
        for (int j = 0; j < 4; j++) acc[i][j] = 0.f;

    int ar = tid >> 2;         // 0..63
    int ak = (tid & 3) * 4;    // 0,4,8,12

    for (int k0 = 0; k0 < K; k0 += GBK) {
#pragma unroll
        for (int rr = 0; rr < 2; rr++) {
            int r = ar + rr * 64;
            float4 v = *(const float4*)(A + (size_t)(bm + r) * K + k0 + ak);
            As[ak + 0][r] = v.x; As[ak + 1][r] = v.y;
            As[ak + 2][r] = v.z; As[ak + 3][r] = v.w;
        }
        {
            float4 v = make_float4(0.f, 0.f, 0.f, 0.f);
            if (bn + ar < N)
                v = *(const float4*)(W + (size_t)(bn + ar) * K + k0 + ak);
            Ws[ak + 0][ar] = v.x; Ws[ak + 1][ar] = v.y;
            Ws[ak + 2][ar] = v.z; Ws[ak + 3][ar] = v.w;
        }
        __syncthreads();
#pragma unroll
        for (int k = 0; k < GBK; k++) {
            float a[8], b[4];
#pragma unroll
            for (int i = 0; i < 8; i++) a[i] = As[k][tm + i];
#pragma unroll
            for (int j = 0; j < 4; j++) b[j] = Ws[k][tn + j];
#pragma unroll
            for (int i = 0; i < 8; i++)
#pragma unroll
                for (int j = 0; j < 4; j++)
                    acc[i][j] = fmaf(a[i], b[j], acc[i][j]);
        }
        __syncthreads();
    }
#pragma unroll
    for (int i = 0; i < 8; i++) {
        int row = bm + tm + i;
#pragma unroll
        for (int j = 0; j < 4; j++) {
            int col = bn + tn + j;
            if (col < N) C[(size_t)row * N + col] = acc[i][j];
        }
    }
}

// ---------------- input transpose: x[B,C,H,W] -> X[(b,h,w)][c] ----------------
__global__ void k_transpose_in(const float* __restrict__ x, float* __restrict__ X) {
    __shared__ float tile[32][33];
    int bh = blockIdx.z;
    int b = bh >> 6, h = bh & 63;
    int w0 = blockIdx.x * 32;
    int c0 = blockIdx.y * 32;
    int tx = threadIdx.x, ty = threadIdx.y;
#pragma unroll
    for (int i = ty; i < 32; i += 8)
        tile[i][tx] = x[((size_t)(b * DM + c0 + i) * 64 + h) * 64 + w0 + tx];
    __syncthreads();
#pragma unroll
    for (int i = ty; i < 32; i += 8)
        X[((size_t)bh * 64 + w0 + i) * DM + c0 + tx] = tile[tx][i];
}

// ---------------- depthwise causal conv + bias + SiLU ----------------
__global__ void __launch_bounds__(256) k_conv(const float* __restrict__ XZ,
                                              const float* __restrict__ convw,
                                              const float* __restrict__ convb,
                                              float* __restrict__ XC2) {
    int seq = blockIdx.x;
    int d = threadIdx.x;
    float w0 = convw[d * 4 + 0], w1 = convw[d * 4 + 1];
    float w2 = convw[d * 4 + 2], w3 = convw[d * 4 + 3];
    float cb = convb[d];
    float x0 = 0.f, x1 = 0.f, x2 = 0.f;
    const float* src = XZ + (size_t)seq * L * (2 * DI) + d;
    float* dst = XC2 + (size_t)seq * L * DI + d;
#pragma unroll 4
    for (int t = 0; t < L; t++) {
        float xt = src[(size_t)t * (2 * DI)];
        float a = fmaf(w0, x0, fmaf(w1, x1, fmaf(w2, x2, fmaf(w3, xt, cb))));
        float sg = 1.f / (1.f + __expf(-a));
        dst[(size_t)t * DI] = a * sg;
        x0 = x1; x1 = x2; x2 = xt;
    }
}

// ---------------- dt = softplus(xdbl[:, :8] @ Wdt^T + bdt) ----------------
__global__ void __launch_bounds__(256) k_dt(const float* __restrict__ XDBL,
                                            const float* __restrict__ Wdt,
                                            const float* __restrict__ bdt,
                                            float* __restrict__ DT) {
    __shared__ float xs[32][DTR];
    int m0 = blockIdx.x * 32;
    int tid = threadIdx.x;
    {
        int t = tid >> 3, r = tid & 7;
        xs[t][r] = XDBL[(size_t)(m0 + t) * XDBL_N + r];
    }
    __syncthreads();
    int d = tid;
    float w[DTR];
#pragma unroll
    for (int r = 0; r < DTR; r++) w[r] = Wdt[d * DTR + r];
    float bd = bdt[d];
    for (int t = 0; t < 32; t++) {
        float s = bd;
#pragma unroll
        for (int r = 0; r < DTR; r++) s = fmaf(xs[t][r], w[r], s);
        float sp = (s > 20.f) ? s : log1pf(__expf(s));
        DT[(size_t)(m0 + t) * DI + d] = sp;
    }
}

// ---------------- selective scan + D skip + silu(z) gate ----------------
__global__ void __launch_bounds__(256) k_scan(const float* __restrict__ XDBL,
                                              const float* __restrict__ DT,
                                              const float* __restrict__ XC2,
                                              const float* __restrict__ XZ,
                                              const float* __restrict__ Alog,
                                              const float* __restrict__ Dvec,
                                              float* __restrict__ Y) {
    __shared__ float sB[L][DS];
    __shared__ float sC[L][DS];
    int seq = blockIdx.x;
    int tid = threadIdx.x;
    for (int i = tid; i < L * 2 * DS; i += 256) {
        int t = i >> 5, j = i & 31;
        float v = XDBL[(size_t)(seq * L + t) * XDBL_N + DTR + j];
        if (j < DS) sB[t][j] = v;
        else        sC[t][j - DS] = v;
    }
    __syncthreads();
    int d = tid;
    float A[DS];
#pragma unroll
    for (int s = 0; s < DS; s++) A[s] = -__expf(Alog[d * DS + s]);
    float Dd = Dvec[d];
    float h[DS];
#pragma unroll
    for (int s = 0; s < DS; s++) h[s] = 0.f;
    for (int t = 0; t < L; t++) {
        size_t m = (size_t)seq * L + t;
        float dt = DT[m * DI + d];
        float xv = XC2[m * DI + d];
        float zv = XZ[m * (2 * DI) + DI + d];
        float dx = dt * xv;
        float acc = 0.f;
#pragma unroll
        for (int s = 0; s < DS; s++) {
            float e = __expf(dt * A[s]);
            h[s] = fmaf(h[s], e, dx * sB[t][s]);
            acc = fmaf(h[s], sC[t][s], acc);
        }
        float y = fmaf(xv, Dd, acc);
        float sg = 1.f / (1.f + __expf(-zv));
        Y[m * DI + d] = y * (zv * sg);
    }
}

// ---------------- inter-pass row permutation: O[(b,h,w)] -> X[(b,w,h)] ----------------
__global__ void k_permute(const float4* __restrict__ src, float4* __restrict__ dst) {
    int gid = blockIdx.x * blockDim.x + threadIdx.x;  // NTOK*32 float4s
    int r = gid >> 5, c = gid & 31;
    int b = r >> 12, h = (r >> 6) & 63, w = r & 63;
    int r2 = (b << 12) | (w << 6) | h;
    dst[(size_t)r2 * 32 + c] = src[(size_t)r * 32 + c];
}

// ---------------- GroupNorm stats: per (b, g) mean + inv-std ----------------
__global__ void __launch_bounds__(256) k_gn_reduce(const float* __restrict__ O,
                                                   float* __restrict__ stats) {
    int bg = blockIdx.x;       // b*4+g
    int b = bg >> 2, g = bg & 3;
    int c0 = g * 32;
    float sum = 0.f, ss = 0.f;
    for (int i = threadIdx.x; i < 32 * 4096; i += 256) {
        int c = c0 + (i & 31);
        int hw = i >> 5;
        float v = O[((size_t)b * 4096 + hw) * DM + c];
        sum += v;
        ss = fmaf(v, v, ss);
    }
    __shared__ float s1[256], s2[256];
    s1[threadIdx.x] = sum; s2[threadIdx.x] = ss;
    __syncthreads();
    for (int st = 128; st > 0; st >>= 1) {
        if (threadIdx.x < st) {
            s1[threadIdx.x] += s1[threadIdx.x + st];
            s2[threadIdx.x] += s2[threadIdx.x + st];
        }
        __syncthreads();
    }
    if (threadIdx.x == 0) {
        float n = 32.f * 4096.f;
        float mu = s1[0] / n;
        float var = s2[0] / n - mu * mu;
        stats[bg * 2]     = mu;
        stats[bg * 2 + 1] = rsqrtf(var + 1e-5f);
    }
}

// ---------------- normalize + SiLU + transpose to (B,C,H,W) ----------------
__global__ void k_gn_write(const float* __restrict__ O, const float* __restrict__ stats,
                           const float* __restrict__ gamma, const float* __restrict__ beta,
                           float* __restrict__ out) {
    __shared__ float tile[32][33];
    int bh = blockIdx.z;
    int b = bh >> 6, h = bh & 63;
    int w0 = blockIdx.x * 32;
    int c0 = blockIdx.y * 32;
    int tx = threadIdx.x, ty = threadIdx.y;
    // O2 layout: [(b,w,h)][c] ; read rows over w, cols over c (coalesced)
#pragma unroll
    for (int i = ty; i < 32; i += 8)
        tile[i][tx] = O[((size_t)(b * 64 + w0 + i) * 64 + h) * DM + c0 + tx];
    __syncthreads();
    int g = c0 >> 5;
    float mu = stats[(b * 4 + g) * 2];
    float istd = stats[(b * 4 + g) * 2 + 1];
#pragma unroll
    for (int i = ty; i < 32; i += 8) {
        int c = c0 + i;
        float v = (tile[tx][i] - mu) * istd * gamma[c] + beta[c];
        float sg = 1.f / (1.f + __expf(-v));
        out[((size_t)(b * DM + c) * 64 + h) * 64 + w0 + tx] = v * sg;
    }
}

// ---------------- host ----------------
extern "C" void kernel_launch(void* const* d_in, const int* in_sizes, int n_in,
                              void* d_out, int out_size) {
    const float* x = (const float*)d_in[0];
    const float* rW[9];
    const float* cW[9];
    for (int i = 0; i < 9; i++) rW[i] = (const float*)d_in[1 + i];
    for (int i = 0; i < 9; i++) cW[i] = (const float*)d_in[10 + i];
    const float* gamma = (const float*)d_in[19];
    const float* beta  = (const float*)d_in[20];
    float* out = (float*)d_out;

    float* buf = nullptr;
    cudaGetSymbolAddress((void**)&buf, g_buf);
    float* X    = buf + OFF_X;
    float* XZ   = buf + OFF_XZ;
    float* XC2  = buf + OFF_XC2;
    float* XDBL = buf + OFF_XDBL;
    float* DT   = buf + OFF_DT;
    float* Y    = buf + OFF_Y;
    float* O    = buf + OFF_O;
    float* ST   = buf + OFF_STATS;

    dim3 tb(32, 8);
    k_transpose_in<<<dim3(2, 4, 512), tb>>>(x, X);

    for (int p = 0; p < 2; p++) {
        const float* const* Wp = (p == 0) ? rW : cW;
        // Wp: 0=Win 1=convw 2=convb 3=Wx 4=Wdt 5=bdt 6=Alog 7=D 8=Wout
        k_gemm<<<dim3((2 * DI) / GBN, NTOK / GBM), 256>>>(X, Wp[0], XZ, NTOK, 2 * DI, DM);
        k_conv<<<NSEQ, 256>>>(XZ, Wp[1], Wp[2], XC2);
        k_gemm<<<dim3(1, NTOK / GBM), 256>>>(XC2, Wp[3], XDBL, NTOK, XDBL_N, DI);
        k_dt<<<NTOK / 32, 256>>>(XDBL, Wp[4], Wp[5], DT);
        k_scan<<<NSEQ, 256>>>(XDBL, DT, XC2, XZ, Wp[6], Wp[7], Y);
        k_gemm<<<dim3(DM / GBN, NTOK / GBM), 256>>>(Y, Wp[8], O, NTOK, DM, DI);
        if (p == 0)
            k_permute<<<(NTOK * 32) / 256, 256>>>((const float4*)O, (float4*)X);
    }

    k_gn_reduce<<<32, 256>>>(O, ST);
    k_gn_write<<<dim3(2, 4, 512), tb>>>(O, ST, gamma, beta, out);
}

// round 4
// speedup vs baseline: 1.5536x; 1.5536x over previous
#include <cuda_runtime.h>
#include <cstdint>

#define NSEQ 512
#define L 64
#define NTOK (NSEQ*L)          // 32768
#define DM 128
#define DI 256
#define DS 16
#define DTR 8
#define XDBL_N (DTR + 2*DS)    // 40

// ---------------- scratch (no allocation allowed) ----------------
#define OFF_X     ((size_t)0)
#define OFF_XZ    (OFF_X    + (size_t)NTOK*DM)
#define OFF_XC2   (OFF_XZ   + (size_t)NTOK*2*DI)
#define OFF_XDBL  (OFF_XC2  + (size_t)NTOK*DI)
#define OFF_DT    (OFF_XDBL + (size_t)NTOK*XDBL_N)
#define OFF_Y     (OFF_DT   + (size_t)NTOK*DI)
#define OFF_O     (OFF_Y    + (size_t)NTOK*DI)
#define OFF_STATS (OFF_O    + (size_t)NTOK*DM)
#define BUF_TOTAL (OFF_STATS + 64)

__device__ float g_buf[BUF_TOTAL];

// ================= tf32 mma.sync GEMM: C[M,N] = A[M,K] @ W[N,K]^T =================
// BM=128, BN=64, BK=32; 256 threads = 8 warps (4x2), warp tile 32x32.
// mma.m16n8k8.row.col : B col-major K×N == W row-major [N,K]. tf32 inputs, fp32 accum.
#define BM 128
#define BN 64
#define BK 32
#define BKP (BK + 4)

__device__ __forceinline__ uint32_t f2tf32(float v) {
    uint32_t r;
    asm("cvt.rna.tf32.f32 %0, %1;" : "=r"(r) : "f"(v));
    return r;
}

__device__ __forceinline__ void mma_tf32(float& c0, float& c1, float& c2, float& c3,
                                         uint32_t a0, uint32_t a1, uint32_t a2, uint32_t a3,
                                         uint32_t b0, uint32_t b1) {
    asm volatile(
        "mma.sync.aligned.m16n8k8.row.col.f32.tf32.tf32.f32 "
        "{%0,%1,%2,%3}, {%4,%5,%6,%7}, {%8,%9}, {%0,%1,%2,%3};"
        : "+f"(c0), "+f"(c1), "+f"(c2), "+f"(c3)
        : "r"(a0), "r"(a1), "r"(a2), "r"(a3), "r"(b0), "r"(b1));
}

__global__ void __launch_bounds__(256) k_gemm_tc(const float* __restrict__ A,
                                                 const float* __restrict__ W,
                                                 float* __restrict__ C,
                                                 int M, int N, int K) {
    __shared__ uint32_t As[BM][BKP];
    __shared__ uint32_t Ws[BN][BKP];
    int tid = threadIdx.x;
    int warp = tid >> 5, lane = tid & 31;
    int wm = (warp >> 1) * 32;   // 0,32,64,96
    int wn = (warp & 1) * 32;    // 0,32
    int bm = blockIdx.x * BM;
    int bn = blockIdx.y * BN;
    int g = lane >> 2, tg = lane & 3;

    float acc[2][4][4];
#pragma unroll
    for (int mi = 0; mi < 2; mi++)
#pragma unroll
        for (int ni = 0; ni < 4; ni++)
#pragma unroll
            for (int j = 0; j < 4; j++) acc[mi][ni][j] = 0.f;

    for (int k0 = 0; k0 < K; k0 += BK) {
        // load A tile: BM rows x 8 float4
#pragma unroll
        for (int i = tid; i < BM * 8; i += 256) {
            int row = i >> 3, q = i & 7;
            float4 v = *(const float4*)(A + (size_t)(bm + row) * K + k0 + q * 4);
            uint4 u = make_uint4(f2tf32(v.x), f2tf32(v.y), f2tf32(v.z), f2tf32(v.w));
            *(uint4*)&As[row][q * 4] = u;
        }
        // load W tile: BN rows x 8 float4 (guarded for N<BN)
#pragma unroll
        for (int i = tid; i < BN * 8; i += 256) {
            int row = i >> 3, q = i & 7;
            float4 v = make_float4(0.f, 0.f, 0.f, 0.f);
            if (bn + row < N)
                v = *(const float4*)(W + (size_t)(bn + row) * K + k0 + q * 4);
            uint4 u = make_uint4(f2tf32(v.x), f2tf32(v.y), f2tf32(v.z), f2tf32(v.w));
            *(uint4*)&Ws[row][q * 4] = u;
        }
        __syncthreads();

#pragma unroll
        for (int kk = 0; kk < BK; kk += 8) {
            uint32_t a[2][4], b[4][2];
#pragma unroll
            for (int mi = 0; mi < 2; mi++) {
                int r0 = wm + mi * 16;
                a[mi][0] = As[r0 + g][kk + tg];
                a[mi][1] = As[r0 + 8 + g][kk + tg];
                a[mi][2] = As[r0 + g][kk + 4 + tg];
                a[mi][3] = As[r0 + 8 + g][kk + 4 + tg];
            }
#pragma unroll
            for (int ni = 0; ni < 4; ni++) {
                int r0 = wn + ni * 8 + g;
                b[ni][0] = Ws[r0][kk + tg];
                b[ni][1] = Ws[r0][kk + 4 + tg];
            }
#pragma unroll
            for (int mi = 0; mi < 2; mi++)
#pragma unroll
                for (int ni = 0; ni < 4; ni++)
                    mma_tf32(acc[mi][ni][0], acc[mi][ni][1], acc[mi][ni][2], acc[mi][ni][3],
                             a[mi][0], a[mi][1], a[mi][2], a[mi][3],
                             b[ni][0], b[ni][1]);
        }
        __syncthreads();
    }

    // epilogue
#pragma unroll
    for (int mi = 0; mi < 2; mi++) {
        int row0 = bm + wm + mi * 16 + g;
#pragma unroll
        for (int ni = 0; ni < 4; ni++) {
            int col = bn + wn + ni * 8 + tg * 2;
            if (col < N) {
                *(float2*)(C + (size_t)row0 * N + col) =
                    make_float2(acc[mi][ni][0], acc[mi][ni][1]);
                *(float2*)(C + (size_t)(row0 + 8) * N + col) =
                    make_float2(acc[mi][ni][2], acc[mi][ni][3]);
            }
        }
    }
}

// ---------------- input transpose: x[B,C,H,W] -> X[(b,h,w)][c] ----------------
__global__ void k_transpose_in(const float* __restrict__ x, float* __restrict__ X) {
    __shared__ float tile[32][33];
    int bh = blockIdx.z;
    int b = bh >> 6, h = bh & 63;
    int w0 = blockIdx.x * 32;
    int c0 = blockIdx.y * 32;
    int tx = threadIdx.x, ty = threadIdx.y;
#pragma unroll
    for (int i = ty; i < 32; i += 8)
        tile[i][tx] = x[((size_t)(b * DM + c0 + i) * 64 + h) * 64 + w0 + tx];
    __syncthreads();
#pragma unroll
    for (int i = ty; i < 32; i += 8)
        X[((size_t)bh * 64 + w0 + i) * DM + c0 + tx] = tile[tx][i];
}

// ---------------- depthwise causal conv + bias + SiLU ----------------
__global__ void __launch_bounds__(256) k_conv(const float* __restrict__ XZ,
                                              const float* __restrict__ convw,
                                              const float* __restrict__ convb,
                                              float* __restrict__ XC2) {
    int seq = blockIdx.x;
    int d = threadIdx.x;
    float w0 = convw[d * 4 + 0], w1 = convw[d * 4 + 1];
    float w2 = convw[d * 4 + 2], w3 = convw[d * 4 + 3];
    float cb = convb[d];
    float x0 = 0.f, x1 = 0.f, x2 = 0.f;
    const float* src = XZ + (size_t)seq * L * (2 * DI) + d;
    float* dst = XC2 + (size_t)seq * L * DI + d;
#pragma unroll 4
    for (int t = 0; t < L; t++) {
        float xt = src[(size_t)t * (2 * DI)];
        float a = fmaf(w0, x0, fmaf(w1, x1, fmaf(w2, x2, fmaf(w3, xt, cb))));
        float sg = 1.f / (1.f + __expf(-a));
        dst[(size_t)t * DI] = a * sg;
        x0 = x1; x1 = x2; x2 = xt;
    }
}

// ---------------- dt = softplus(xdbl[:, :8] @ Wdt^T + bdt) ----------------
__global__ void __launch_bounds__(256) k_dt(const float* __restrict__ XDBL,
                                            const float* __restrict__ Wdt,
                                            const float* __restrict__ bdt,
                                            float* __restrict__ DT) {
    __shared__ float xs[32][DTR];
    int m0 = blockIdx.x * 32;
    int tid = threadIdx.x;
    {
        int t = tid >> 3, r = tid & 7;
        xs[t][r] = XDBL[(size_t)(m0 + t) * XDBL_N + r];
    }
    __syncthreads();
    int d = tid;
    float w[DTR];
#pragma unroll
    for (int r = 0; r < DTR; r++) w[r] = Wdt[d * DTR + r];
    float bd = bdt[d];
    for (int t = 0; t < 32; t++) {
        float s = bd;
#pragma unroll
        for (int r = 0; r < DTR; r++) s = fmaf(xs[t][r], w[r], s);
        float sp = (s > 20.f) ? s : log1pf(__expf(s));
        DT[(size_t)(m0 + t) * DI + d] = sp;
    }
}

// ---------------- selective scan + D skip + silu(z) gate ----------------
__global__ void __launch_bounds__(256) k_scan(const float* __restrict__ XDBL,
                                              const float* __restrict__ DT,
                                              const float* __restrict__ XC2,
                                              const float* __restrict__ XZ,
                                              const float* __restrict__ Alog,
                                              const float* __restrict__ Dvec,
                                              float* __restrict__ Y) {
    __shared__ float sB[L][DS];
    __shared__ float sC[L][DS];
    int seq = blockIdx.x;
    int tid = threadIdx.x;
    for (int i = tid; i < L * 2 * DS; i += 256) {
        int t = i >> 5, j = i & 31;
        float v = XDBL[(size_t)(seq * L + t) * XDBL_N + DTR + j];
        if (j < DS) sB[t][j] = v;
        else        sC[t][j - DS] = v;
    }
    __syncthreads();
    int d = tid;
    float A[DS];
#pragma unroll
    for (int s = 0; s < DS; s++) A[s] = -__expf(Alog[d * DS + s]);
    float Dd = Dvec[d];
    float h[DS];
#pragma unroll
    for (int s = 0; s < DS; s++) h[s] = 0.f;
    for (int t = 0; t < L; t++) {
        size_t m = (size_t)seq * L + t;
        float dt = DT[m * DI + d];
        float xv = XC2[m * DI + d];
        float zv = XZ[m * (2 * DI) + DI + d];
        float dx = dt * xv;
        float acc = 0.f;
#pragma unroll
        for (int s = 0; s < DS; s++) {
            float e = __expf(dt * A[s]);
            h[s] = fmaf(h[s], e, dx * sB[t][s]);
            acc = fmaf(h[s], sC[t][s], acc);
        }
        float y = fmaf(xv, Dd, acc);
        float sg = 1.f / (1.f + __expf(-zv));
        Y[m * DI + d] = y * (zv * sg);
    }
}

// ---------------- inter-pass row permutation ----------------
__global__ void k_permute(const float4* __restrict__ src, float4* __restrict__ dst) {
    int gid = blockIdx.x * blockDim.x + threadIdx.x;
    int r = gid >> 5, c = gid & 31;
    int b = r >> 12, h = (r >> 6) & 63, w = r & 63;
    int r2 = (b << 12) | (w << 6) | h;
    dst[(size_t)r2 * 32 + c] = src[(size_t)r * 32 + c];
}

// ---------------- GroupNorm stats ----------------
__global__ void __launch_bounds__(256) k_gn_reduce(const float* __restrict__ O,
                                                   float* __restrict__ stats) {
    int bg = blockIdx.x;
    int b = bg >> 2, g = bg & 3;
    int c0 = g * 32;
    float sum = 0.f, ss = 0.f;
    for (int i = threadIdx.x; i < 32 * 4096; i += 256) {
        int c = c0 + (i & 31);
        int hw = i >> 5;
        float v = O[((size_t)b * 4096 + hw) * DM + c];
        sum += v;
        ss = fmaf(v, v, ss);
    }
    __shared__ float s1[256], s2[256];
    s1[threadIdx.x] = sum; s2[threadIdx.x] = ss;
    __syncthreads();
    for (int st = 128; st > 0; st >>= 1) {
        if (threadIdx.x < st) {
            s1[threadIdx.x] += s1[threadIdx.x + st];
            s2[threadIdx.x] += s2[threadIdx.x + st];
        }
        __syncthreads();
    }
    if (threadIdx.x == 0) {
        float n = 32.f * 4096.f;
        float mu = s1[0] / n;
        float var = s2[0] / n - mu * mu;
        stats[bg * 2] = mu;
        stats[bg * 2 + 1] = rsqrtf(var + 1e-5f);
    }
}

// ---------------- normalize + SiLU + transpose out ----------------
__global__ void k_gn_write(const float* __restrict__ O, const float* __restrict__ stats,
                           const float* __restrict__ gamma, const float* __restrict__ beta,
                           float* __restrict__ out) {
    __shared__ float tile[32][33];
    int bh = blockIdx.z;
    int b = bh >> 6, h = bh & 63;
    int w0 = blockIdx.x * 32;
    int c0 = blockIdx.y * 32;
    int tx = threadIdx.x, ty = threadIdx.y;
#pragma unroll
    for (int i = ty; i < 32; i += 8)
        tile[i][tx] = O[((size_t)(b * 64 + w0 + i) * 64 + h) * DM + c0 + tx];
    __syncthreads();
    int g = c0 >> 5;
    float mu = stats[(b * 4 + g) * 2];
    float istd = stats[(b * 4 + g) * 2 + 1];
#pragma unroll
    for (int i = ty; i < 32; i += 8) {
        int c = c0 + i;
        float v = (tile[tx][i] - mu) * istd * gamma[c] + beta[c];
        float sg = 1.f / (1.f + __expf(-v));
        out[((size_t)(b * DM + c) * 64 + h) * 64 + w0 + tx] = v * sg;
    }
}

// ---------------- host ----------------
extern "C" void kernel_launch(void* const* d_in, const int* in_sizes, int n_in,
                              void* d_out, int out_size) {
    const float* x = (const float*)d_in[0];
    const float* rW[9];
    const float* cW[9];
    for (int i = 0; i < 9; i++) rW[i] = (const float*)d_in[1 + i];
    for (int i = 0; i < 9; i++) cW[i] = (const float*)d_in[10 + i];
    const float* gamma = (const float*)d_in[19];
    const float* beta  = (const float*)d_in[20];
    float* out = (float*)d_out;

    float* buf = nullptr;
    cudaGetSymbolAddress((void**)&buf, g_buf);
    float* X    = buf + OFF_X;
    float* XZ   = buf + OFF_XZ;
    float* XC2  = buf + OFF_XC2;
    float* XDBL = buf + OFF_XDBL;
    float* DT   = buf + OFF_DT;
    float* Y    = buf + OFF_Y;
    float* O    = buf + OFF_O;
    float* ST   = buf + OFF_STATS;

    dim3 tb(32, 8);
    k_transpose_in<<<dim3(2, 4, 512), tb>>>(x, X);

    for (int p = 0; p < 2; p++) {
        const float* const* Wp = (p == 0) ? rW : cW;
        // 0=Win 1=convw 2=convb 3=Wx 4=Wdt 5=bdt 6=Alog 7=D 8=Wout
        k_gemm_tc<<<dim3(NTOK / BM, (2 * DI) / BN), 256>>>(X, Wp[0], XZ, NTOK, 2 * DI, DM);
        k_conv<<<NSEQ, 256>>>(XZ, Wp[1], Wp[2], XC2);
        k_gemm_tc<<<dim3(NTOK / BM, 1), 256>>>(XC2, Wp[3], XDBL, NTOK, XDBL_N, DI);
        k_dt<<<NTOK / 32, 256>>>(XDBL, Wp[4], Wp[5], DT);
        k_scan<<<NSEQ, 256>>>(XDBL, DT, XC2, XZ, Wp[6], Wp[7], Y);
        k_gemm_tc<<<dim3(NTOK / BM, DM / BN), 256>>>(Y, Wp[8], O, NTOK, DM, DI);
        if (p == 0)
            k_permute<<<(NTOK * 32) / 256, 256>>>((const float4*)O, (float4*)X);
    }

    k_gn_reduce<<<32, 256>>>(O, ST);
    k_gn_write<<<dim3(2, 4, 512), tb>>>(O, ST, gamma, beta, out);
}